// round 16
// baseline (speedup 1.0000x reference)
#include <cuda_runtime.h>
#include <cuda_fp16.h>

#define D 64
#define ALPHA 0.2f
#define MAX_N 131072
#define MAX_E 2200000
#define SCAN_B 512

// Static scratch (BSS zero-init). Replay invariants: k_aggregate reads+zeros
// g_cnt; k_pre_hist zeroes g_total.
__device__ int     g_cnt[MAX_N];
__device__ int     g_rowptr[MAX_N];
__device__ int     g_total;
__device__ int     g_slot[MAX_E];     // per-edge within-row slot from hist
__device__ float4  g_rec[MAX_E];      // per-edge record: (w0, w1, col_bits, -)
__device__ float2  g_s1[MAX_N];       // per-node source-side scores (h0,h1)
__device__ float2  g_s2[MAX_N];       // per-node dest-side scores (h0,h1)

// Packed f32x2 helpers (Blackwell FFMA2 — only reachable via PTX).
__device__ __forceinline__ void ffma2(unsigned long long& acc, float w, float2 xv) {
    asm("{\n\t"
        ".reg .b64 wp, xp;\n\t"
        "mov.b64 wp, {%1, %1};\n\t"
        "mov.b64 xp, {%2, %3};\n\t"
        "fma.rn.f32x2 %0, wp, xp, %0;\n\t"
        "}" : "+l"(acc) : "f"(w), "f"(xv.x), "f"(xv.y));
}
__device__ __forceinline__ void fadd2(unsigned long long& acc, float a, float b) {
    asm("{\n\t"
        ".reg .b64 t;\n\t"
        "mov.b64 t, {%1, %2};\n\t"
        "add.rn.f32x2 %0, t, %0;\n\t"
        "}" : "+l"(acc) : "f"(a), "f"(b));
}
__device__ __forceinline__ float2 unpack2(unsigned long long v) {
    float lo, hi;
    asm("mov.b64 {%0, %1}, %2;" : "=f"(lo), "=f"(hi) : "l"(v));
    return make_float2(lo, hi);
}

// Fused: blocks [0,nbE) do the edge histogram; blocks [nbE,...) do per-node
// scores, FOUR nodes per warp (4 independent DRAM loads in flight — R14-
// validated). No fp16 conversion anymore (aggregate reads x directly).
__global__ void k_pre_hist(const float* __restrict__ x,
                           const float* __restrict__ W,
                           const float* __restrict__ a,
                           const int* __restrict__ row,
                           int n, int E, int nbE) {
    int t = threadIdx.x;
    if ((int)blockIdx.x < nbE) {
        if (blockIdx.x == 0 && t == 0) g_total = 0;   // replay reset
        int i = blockIdx.x * blockDim.x + t;
        if (i < E) g_slot[i] = atomicAdd(&g_cnt[row[i]], 1);
        return;
    }
    __shared__ float v00[64], v01[64], v10[64], v11[64]; // W[h][j]*a[h][..j]
    if (t < 64) {
        float w0 = W[t], w1 = W[64 + t];
        v00[t] = w0 * a[t];
        v01[t] = w0 * a[64 + t];
        v10[t] = w1 * a[128 + t];
        v11[t] = w1 * a[192 + t];
    }
    __syncthreads();
    int b = blockIdx.x - nbE;
    int warp = (b * blockDim.x + t) >> 5;   // warp handles nodes 4w..4w+3
    int lane = t & 31;
    int base = warp * 4;
    if (base >= n) return;
    const float2* __restrict__ x2 = reinterpret_cast<const float2*>(x);
    float2 xv[4];
    int nk = min(4, n - base);
    #pragma unroll
    for (int k = 0; k < 4; k++)
        if (k < nk) xv[k] = x2[(base + k) * 32 + lane];   // 4 indep loads
    int l2 = lane * 2;
    float c00a = v00[l2], c00b = v00[l2 + 1];
    float c01a = v01[l2], c01b = v01[l2 + 1];
    float c10a = v10[l2], c10b = v10[l2 + 1];
    float c11a = v11[l2], c11b = v11[l2 + 1];
    #pragma unroll
    for (int k = 0; k < 4; k++) {
        if (k >= nk) break;
        float s10 = xv[k].x * c00a + xv[k].y * c00b;
        float s20 = xv[k].x * c01a + xv[k].y * c01b;
        float s11 = xv[k].x * c10a + xv[k].y * c10b;
        float s21 = xv[k].x * c11a + xv[k].y * c11b;
        // 6-SHFL multi-value butterfly
        float u0 = (lane < 16 ? s10 : s20)
                 + __shfl_xor_sync(0xffffffffu, (lane < 16 ? s20 : s10), 16);
        float u1 = (lane < 16 ? s11 : s21)
                 + __shfl_xor_sync(0xffffffffu, (lane < 16 ? s21 : s11), 16);
        float v = ((lane & 8) ? u1 : u0)
                + __shfl_xor_sync(0xffffffffu, ((lane & 8) ? u0 : u1), 8);
        v += __shfl_xor_sync(0xffffffffu, v, 4);
        v += __shfl_xor_sync(0xffffffffu, v, 2);
        v += __shfl_xor_sync(0xffffffffu, v, 1);
        if (lane == 0)  g_s1[base + k].x = v;
        if (lane == 8)  g_s1[base + k].y = v;
        if (lane == 16) g_s2[base + k].x = v;
        if (lane == 24) g_s2[base + k].y = v;
    }
}

// Single-pass scan: block-local exclusive scan of g_cnt; block claims its
// base with one atomicAdd. Row ranges are disjoint (sufficient); g_cnt kept
// as per-node degree for aggregate (which resets it).
__global__ void k_scan(int n) {
    __shared__ int sh[SCAN_B];
    __shared__ int base_sh;
    int t = threadIdx.x;
    int i = blockIdx.x * SCAN_B + t;
    int vv = (i < n) ? g_cnt[i] : 0;
    sh[t] = vv;
    __syncthreads();
    #pragma unroll
    for (int o = 1; o < SCAN_B; o <<= 1) {
        int tmp = (t >= o) ? sh[t - o] : 0;
        __syncthreads();
        sh[t] += tmp;
        __syncthreads();
    }
    if (t == SCAN_B - 1) base_sh = atomicAdd(&g_total, sh[t]);
    __syncthreads();
    if (i < n) g_rowptr[i] = base_sh + sh[t] - vv;
}

// Edge-parallel CSR fill (atomic-free): both head weights in fp32, packed
// with the column index into one always-aligned 16-byte record.
__global__ void k_scatter(const int* __restrict__ row,
                          const int* __restrict__ col, int E) {
    int i = blockIdx.x * blockDim.x + threadIdx.x;
    if (i >= E) return;
    int r = row[i], c = col[i];
    int pos = g_rowptr[r] + g_slot[i];
    float2 s1 = g_s1[r];
    float2 s2 = g_s2[c];
    float sc0 = s1.x + s2.x;
    float sc1 = s1.y + s2.y;
    float w0 = __expf(sc0 > 0.f ? sc0 : ALPHA * sc0);
    float w1 = __expf(sc1 > 0.f ? sc1 : ALPHA * sc1);
    g_rec[pos] = make_float4(w0, w1, __int_as_float(c), 0.f);
}

// One warp per node. Same pair-shape as the proven R12/R15 loop (two record
// loads + two independent x gathers per iteration) but fp32 end-to-end and
// f32x2 packed math: per edge = 1 LDG.128 + 1 LDG.64 + 2 FFMA2 + 1 FADD2,
// zero converts. Resets g_cnt for the next graph replay.
__global__ void k_aggregate(const float* __restrict__ x,
                            float* __restrict__ out, int n) {
    int warp = (blockIdx.x * blockDim.x + threadIdx.x) >> 5;
    int lane = threadIdx.x & 31;
    if (warp >= n) return;
    int beg = g_rowptr[warp];
    int deg = g_cnt[warp];
    if (lane == 0) g_cnt[warp] = 0;
    int end = beg + deg;
    const float2* __restrict__ x2 = reinterpret_cast<const float2*>(x);
    unsigned long long acc0 = 0ull, acc1 = 0ull, rs = 0ull; // (a00,a01),(a10,a11),(rs0,rs1)

    int e = beg;
    for (; e + 1 < end; e += 2) {      // pair: 2 recs + 2 indep gathers
        float4 r0 = g_rec[e];
        float4 r1 = g_rec[e + 1];
        int c0 = __float_as_int(r0.z);
        int c1 = __float_as_int(r1.z);
        float2 xv0 = x2[c0 * 32 + lane];
        float2 xv1 = x2[c1 * 32 + lane];
        ffma2(acc0, r0.x, xv0);
        ffma2(acc1, r0.y, xv0);
        fadd2(rs, r0.x, r0.y);
        ffma2(acc0, r1.x, xv1);
        ffma2(acc1, r1.y, xv1);
        fadd2(rs, r1.x, r1.y);
    }
    if (e < end) {                     // tail (records always 16B-aligned)
        float4 r0 = g_rec[e];
        int c0 = __float_as_int(r0.z);
        float2 xv0 = x2[c0 * 32 + lane];
        ffma2(acc0, r0.x, xv0);
        ffma2(acc1, r0.y, xv0);
        fadd2(rs, r0.x, r0.y);
    }

    float2 A0 = unpack2(acc0);         // (a00, a01)
    float2 A1 = unpack2(acc1);         // (a10, a11)
    float2 R  = unpack2(rs);           // (rs0, rs1)
    float i0 = 0.5f / R.x, i1 = 0.5f / R.y;
    float2 o;
    o.x = A0.x * i0 + A1.x * i1;
    o.y = A0.y * i0 + A1.y * i1;
    reinterpret_cast<float2*>(out)[warp * 32 + lane] = o;
}

extern "C" void kernel_launch(void* const* d_in, const int* in_sizes, int n_in,
                              void* d_out, int out_size) {
    const float* x  = (const float*)d_in[0];
    const int*   ei = (const int*)d_in[1];
    const float* W  = (const float*)d_in[2];
    const float* a  = (const float*)d_in[3];
    float* out = (float*)d_out;

    int n = in_sizes[0] / D;
    int E = in_sizes[1] / 2;
    const int* row = ei;
    const int* col = ei + E;

    const int T = 256;
    int nbE = (E + T - 1) / T;
    int nodes4 = (n + 3) / 4;                    // 4 nodes per warp in pre
    int nbP = (nodes4 * 32 + T - 1) / T;
    int nbW = (n * 32 + T - 1) / T;              // one warp per node
    int nbS = (n + SCAN_B - 1) / SCAN_B;

    k_pre_hist<<<nbE + nbP, T>>>(x, W, a, row, n, E, nbE);
    k_scan<<<nbS, SCAN_B>>>(n);
    k_scatter<<<nbE, T>>>(row, col, E);
    k_aggregate<<<nbW, T>>>(x, out, n);
}